// round 14
// baseline (speedup 1.0000x reference)
#include <cuda_runtime.h>
#include <cuda_bf16.h>
#include <cuda_fp16.h>
#include <cub/cub.cuh>
#include <cstdint>
#include <math.h>

typedef unsigned long long u64;
typedef unsigned int u32;

// ---------------------------------------------------------------------------
// Problem constants
// ---------------------------------------------------------------------------
#define NLVL 5
#define ATOT 261888
#define MCAND 21840
#define POST_K 1000
#define NMS_T 0.7f
#define SCALE_CLAMP 4.135166556742356f
#define TOTHW 87296
#define MASK_PER_BATCH 3697344
#define REM_WORDS 684

#define OUT_KB   2618880
#define OUT_KS   2626880
#define OUT_VALID 2628880

// prescale: A x 2^13, B x 2^10, output x 2^-23
#define A_SCALE 8192.0f
#define B_SCALE 1024.0f
#define OUT_SCALE 1.1920928955078125e-07f   // 2^-23

#define NXEL 22347776u   // 2 * 128 * TOTHW

__constant__ int c_COFF[5]  = {0, 6000, 12000, 18000, 21072};
__constant__ int c_K[5]     = {6000, 6000, 6000, 3072, 768};
__constant__ int c_W32[5]   = {188, 188, 188, 96, 24};
__constant__ int c_RWOFF[5] = {0, 188, 376, 564, 660};
__constant__ int c_MOFF[5]  = {0, 1128000, 2256000, 3384000, 3678912};
__constant__ int c_AOFF[5]  = {0, 196608, 245760, 258048, 261120};
__constant__ int c_LW[5]    = {256, 128, 64, 32, 16};
__constant__ int c_STR[5]   = {4, 8, 16, 32, 64};
__constant__ int c_SZ[5]    = {32, 64, 128, 256, 512};
__constant__ int c_HWOFF[5] = {0, 65536, 81920, 86016, 87040};

// ---------------------------------------------------------------------------
// Static device scratch
// ---------------------------------------------------------------------------
__device__ float  g_t[2u * 256u * TOTHW];      // conv outputs, [n][co][TOTHW]
// A weights, f16x3 split (prescaled), fragment-packed u32 (2 f16/u32)
__device__ u32    g_wA32[884736];
// activations pre-split: [n][pair p][TOTHW] u32 = {f16 ch 2p, f16 ch 2p+1}
__device__ u32    g_x0[NXEL];
__device__ u32    g_x1[NXEL];
__device__ u32    g_x2[NXEL];
__device__ u64    g_keys[2 * ATOT];
__device__ u64    g_keyso[2 * ATOT];
__device__ float  g_boxes[2 * MCAND * 4];
__device__ float  g_scores[2 * MCAND];
__device__ u64    g_k2[2 * MCAND];
__device__ u64    g_k2o[2 * MCAND];
__device__ u32    g_mask[2u * MASK_PER_BATCH];
__device__ unsigned char g_cubtmp[48u * 1024u * 1024u];

__device__ __forceinline__ int lvl_of_c(int c) {
    return (c < 6000) ? 0 : (c < 12000) ? 1 : (c < 18000) ? 2 : (c < 21072) ? 3 : 4;
}
__device__ __forceinline__ int lvl_of_g(int g) {
    return (g < 196608) ? 0 : (g < 245760) ? 1 : (g < 258048) ? 2 : (g < 261120) ? 3 : 4;
}

__device__ __forceinline__ u32 s2u(const void* p) { return (u32)__cvta_generic_to_shared(p); }
__device__ __forceinline__ void cpa16(u32 d, const void* s) {
    asm volatile("cp.async.cg.shared.global [%0], [%1], 16;" :: "r"(d), "l"(s));
}
__device__ __forceinline__ void cpa4z(u32 d, const void* s, int sz) {
    asm volatile("cp.async.ca.shared.global [%0], [%1], 4, %2;" :: "r"(d), "l"(s), "r"(sz));
}
#define CPA_COMMIT() asm volatile("cp.async.commit_group;")
#define CPA_WAIT1()  asm volatile("cp.async.wait_group 1;")
__device__ __forceinline__ void pref_l2(const void* p) {
    asm volatile("prefetch.global.L2 [%0];" :: "l"(p));
}

// f16 helpers
__device__ __forceinline__ u32 pack_h2(float lo, float hi) {
    __half2 t = __floats2half2_rn(lo, hi);
    return *(u32*)&t;
}

#define MMAH(D, A, B0, B1) \
    asm volatile("mma.sync.aligned.m16n8k16.row.col.f32.f16.f16.f32 " \
        "{%0,%1,%2,%3},{%4,%5,%6,%7},{%8,%9},{%0,%1,%2,%3};" \
        : "+f"((D).x), "+f"((D).y), "+f"((D).z), "+f"((D).w) \
        : "r"((A).x), "r"((A).y), "r"((A).z), "r"((A).w), "r"(B0), "r"(B1))

struct ConvPtrs { const float* f[5]; };

// ---------------------------------------------------------------------------
// Weight transform: conv_w [co][ci][3][3] -> f16x3 (prescaled) fragment u32
// ---------------------------------------------------------------------------
__global__ void wtrans_tc(const float* __restrict__ w) {
    int e = blockIdx.x * 256 + threadIdx.x;
    if (e >= 884736) return;
    int s = e / 294912;
    int rem = e - s * 294912;
    int h = rem / 147456;
    int rem2 = rem - h * 147456;
    int kc = rem2 >> 11;
    int idx = rem2 & 2047;
    int ks2 = idx >> 10;
    int mt = (idx >> 7) & 7;
    int lane = (idx >> 2) & 31;
    int r = idx & 3;
    int row_local = mt * 16 + (r & 1) * 8 + (lane >> 2);
    int co = h * 128 + row_local;
    int kbase = kc * 32 + ks2 * 16 + (r >> 1) * 8 + (lane & 3) * 2;
    float sel[2];
#pragma unroll
    for (int half = 0; half < 2; half++) {
        int kg = kbase + half;
        int tap = kg >> 8, ci = kg & 255;
        float v = w[co * 2304 + ci * 9 + tap] * A_SCALE;
        float b0 = __half2float(__float2half_rn(v));
        float r1 = v - b0;
        float b1 = __half2float(__float2half_rn(r1));
        float r2 = r1 - b1;
        sel[half] = (s == 0) ? b0 : (s == 1) ? b1 : r2;
    }
    g_wA32[e] = pack_h2(sel[0], sel[1]);
}

// ---------------------------------------------------------------------------
// Activation pre-split: f[l] -> g_x0/1/2 channel-pair-packed f16 (prescaled)
// e = (n*128 + p)*TOTHW + hw
// ---------------------------------------------------------------------------
__global__ void xtrans(ConvPtrs P) {
    u32 e = blockIdx.x * 256 + threadIdx.x;
    if (e >= NXEL) return;
    int hw = (int)(e % TOTHW);
    int rest = (int)(e / TOTHW);
    int p = rest & 127, n = rest >> 7;
    int l = (hw < 65536) ? 0 : (hw < 81920) ? 1 : (hw < 86016) ? 2 : (hw < 87040) ? 3 : 4;
    int W = c_LW[l], HW = W * W;
    int off = hw - c_HWOFF[l];
    const float* src = P.f[l] + ((size_t)n * 256 + 2 * p) * HW + off;
    float v0 = src[0] * B_SCALE;
    float v1 = src[HW] * B_SCALE;
    float a0 = __half2float(__float2half_rn(v0));
    float ra = v0 - a0;
    float a1 = __half2float(__float2half_rn(ra));
    float a2 = ra - a1;
    float b0 = __half2float(__float2half_rn(v1));
    float rb = v1 - b0;
    float b1 = __half2float(__float2half_rn(rb));
    float b2 = rb - b1;
    g_x0[e] = pack_h2(a0, b0);
    g_x1[e] = pack_h2(a1, b1);
    g_x2[e] = pack_h2(a2, b2);
}

__global__ void dummy_k() {}

// ---------------------------------------------------------------------------
// f16x3 6-pass mma.sync conv, per-chunk flush, 3-buffer cp.async pipeline.
// B staging is pure cp.async (splits precomputed in xtrans).
// smem: A panels [s][buf] 9x8KB, B panels [s][buf] 9x8KB -> 144KB
// ---------------------------------------------------------------------------
#define PANEL 8192
#define SB0 73728
#define CONV_SMEM 147456

__global__ __launch_bounds__(256, 1)
void conv_mma_kernel(ConvPtrs P, const float* __restrict__ bias) {
    const int b = blockIdx.x;
    const int h = b & 1, nb = (b >> 1) & 1;
    const int t = b >> 2;          // 0..681
    const int l = (t < 512) ? 0 : (t < 640) ? 1 : (t < 672) ? 2 : (t < 680) ? 3 : 4;
    const int sbase = (l == 0) ? 0 : (l == 1) ? 512 : (l == 2) ? 640 : (l == 3) ? 672 : 680;
    const int hw0 = (t - sbase) * 128;
    const int W = c_LW[l], H = W;
    const int lw = (l == 0) ? 8 : (l == 1) ? 7 : (l == 2) ? 6 : (l == 3) ? 5 : 4;
    const int hwoff = c_HWOFF[l];

    extern __shared__ __align__(16) char smem[];
    const u32 smb = s2u(smem);
    const int tid = threadIdx.x;
    const int wid = tid >> 5, lane = tid & 31;

    const int wm = wid & 3, wn = wid >> 2;
    const int kh = wid >> 2, nh = wid & 3;
    const int nI = nh * 32 + lane;
    const int yI = (hw0 + nI) >> lw, xI = (hw0 + nI) & (W - 1);
    const int ntI = nI >> 3, gidI = nI & 7;
    const int ntpI = ntI >> 1, ceI = (ntI & 1) * 2;

    float4 acc[2][8];
#pragma unroll
    for (int f = 0; f < 2; f++)
#pragma unroll
        for (int q = 0; q < 8; q++) acc[f][q] = make_float4(0.f, 0.f, 0.f, 0.f);

    auto stageA = [&](int kc, int buf) {
#pragma unroll
        for (int s = 0; s < 3; s++) {
            const u32* src = g_wA32 + (size_t)((s * 2 + h) * 72 + kc) * 2048;
            u32 dst = smb + (u32)((s * 3 + buf) * PANEL);
            for (int i = tid; i < 512; i += 256) cpa16(dst + i * 16, src + i * 4);
        }
    };
    auto stageB = [&](int kc, int buf) {
        int tap = kc >> 3;
        int dy = tap / 3 - 1, dx = tap - (tap / 3) * 3 - 1;
        int yy = yI + dy, xx = xI + dx;
        bool valid = ((unsigned)yy < (unsigned)H) & ((unsigned)xx < (unsigned)W);
        int pix = valid ? (hwoff + yy * W + xx) : 0;
        int sz = valid ? 4 : 0;
        int p0 = (kc & 7) * 16 + kh * 8;
        size_t sb = ((size_t)nb * 128 + p0) * TOTHW + pix;
        u32 d0 = smb + SB0 + (u32)((0 * 3 + buf) * PANEL);
        u32 d1 = smb + SB0 + (u32)((1 * 3 + buf) * PANEL);
        u32 d2 = smb + SB0 + (u32)((2 * 3 + buf) * PANEL);
        u32 iub = (u32)(kh * 1024 + ntpI * 128 + ceI);
#pragma unroll
        for (int j = 0; j < 8; j++) {
            u32 doff = (iub + (u32)((gidI * 4 + (j & 3)) * 4 + (j >> 2))) * 4;
            size_t so = sb + (size_t)j * TOTHW;
            cpa4z(d0 + doff, g_x0 + so, sz);
            cpa4z(d1 + doff, g_x1 + so, sz);
            cpa4z(d2 + doff, g_x2 + so, sz);
        }
    };
    auto mmaC = [&](int buf) {
        const uint4* As[3]; const uint4* Bs[3];
#pragma unroll
        for (int s = 0; s < 3; s++) {
            As[s] = (const uint4*)(smem + (s * 3 + buf) * PANEL);
            Bs[s] = (const uint4*)(smem + SB0 + (s * 3 + buf) * PANEL);
        }
        float4 cacc[2][8];
#pragma unroll
        for (int f = 0; f < 2; f++)
#pragma unroll
            for (int q = 0; q < 8; q++) cacc[f][q] = make_float4(0.f, 0.f, 0.f, 0.f);

#pragma unroll
        for (int ks2 = 0; ks2 < 2; ks2++) {
            uint4 a[3][2];
#pragma unroll
            for (int s = 0; s < 3; s++)
#pragma unroll
                for (int f = 0; f < 2; f++)
                    a[s][f] = As[s][ks2 * 256 + (wm * 2 + f) * 32 + lane];
#pragma unroll
            for (int q = 0; q < 4; q++) {
                uint4 b0q = Bs[0][ks2 * 256 + (wn * 4 + q) * 32 + lane];
                uint4 b1q = Bs[1][ks2 * 256 + (wn * 4 + q) * 32 + lane];
                uint4 b2q = Bs[2][ks2 * 256 + (wn * 4 + q) * 32 + lane];
#pragma unroll
                for (int f = 0; f < 2; f++) {
                    float4& dE = cacc[f][2 * q];
                    float4& dO = cacc[f][2 * q + 1];
                    MMAH(dE, a[0][f], b0q.x, b0q.y); MMAH(dO, a[0][f], b0q.z, b0q.w);
                    MMAH(dE, a[0][f], b1q.x, b1q.y); MMAH(dO, a[0][f], b1q.z, b1q.w);
                    MMAH(dE, a[1][f], b0q.x, b0q.y); MMAH(dO, a[1][f], b0q.z, b0q.w);
                    MMAH(dE, a[1][f], b1q.x, b1q.y); MMAH(dO, a[1][f], b1q.z, b1q.w);
                    MMAH(dE, a[0][f], b2q.x, b2q.y); MMAH(dO, a[0][f], b2q.z, b2q.w);
                    MMAH(dE, a[2][f], b0q.x, b0q.y); MMAH(dO, a[2][f], b0q.z, b0q.w);
                }
            }
        }
#pragma unroll
        for (int f = 0; f < 2; f++)
#pragma unroll
            for (int q = 0; q < 8; q++) {
                acc[f][q].x += cacc[f][q].x;
                acc[f][q].y += cacc[f][q].y;
                acc[f][q].z += cacc[f][q].z;
                acc[f][q].w += cacc[f][q].w;
            }
    };

    // prologue: stage chunks 0 and 1
    stageA(0, 0); stageB(0, 0); CPA_COMMIT();
    stageA(1, 1); stageB(1, 1); CPA_COMMIT();
    CPA_WAIT1();              // chunk 0 ready
    __syncthreads();

#pragma unroll 1
    for (int kc = 0; kc < 72; kc++) {
        int nx = kc + 2;
        if (nx < 72) { stageA(nx, nx - (nx / 3) * 3); stageB(nx, nx - (nx / 3) * 3); }
        CPA_COMMIT();         // one group per iteration (possibly empty)
        mmaC(kc - (kc / 3) * 3);
        CPA_WAIT1();          // chunk kc+1 ready
        __syncthreads();
    }

    // epilogue: unscale + bias + relu, scatter fragments
#pragma unroll
    for (int f = 0; f < 2; f++) {
        int r0 = wm * 32 + f * 16 + (lane >> 2);
        float bv0 = bias[h * 128 + r0];
        float bv1 = bias[h * 128 + r0 + 8];
        float* d0 = g_t + (size_t)(nb * 256 + h * 128 + r0) * TOTHW + hwoff + hw0;
        float* d1 = d0 + (size_t)8 * TOTHW;
#pragma unroll
        for (int q = 0; q < 8; q++) {
            int n0 = wn * 64 + q * 8 + (lane & 3) * 2;
            float4 dd = acc[f][q];
            float2 o0, o1;
            o0.x = fmaxf(fmaf(dd.x, OUT_SCALE, bv0), 0.f);
            o0.y = fmaxf(fmaf(dd.y, OUT_SCALE, bv0), 0.f);
            o1.x = fmaxf(fmaf(dd.z, OUT_SCALE, bv1), 0.f);
            o1.y = fmaxf(fmaf(dd.w, OUT_SCALE, bv1), 0.f);
            *(float2*)(d0 + n0) = o0;
            *(float2*)(d1 + n0) = o1;
        }
    }
}

// ---------------------------------------------------------------------------
// Fused 1x1 heads
// ---------------------------------------------------------------------------
__global__ __launch_bounds__(256)
void head_fused_kernel(const float* __restrict__ ow, const float* __restrict__ ob,
                       const float* __restrict__ dw, const float* __restrict__ db,
                       float* __restrict__ out) {
    __shared__ float sW[15 * 256];
    int tid = threadIdx.x;
    for (int i = tid; i < 3840; i += 256) {
        int k = i >> 8, ci = i & 255;
        sW[i] = (k < 3) ? ow[k * 256 + ci] : dw[(k - 3) * 256 + ci];
    }
    __syncthreads();
    int b = blockIdx.x, n = blockIdx.z;
    int l, hw0, cnt = 1024;
    if (b < 64)      { l = 0; hw0 = b << 10; }
    else if (b < 80) { l = 1; hw0 = (b - 64) << 10; }
    else if (b < 84) { l = 2; hw0 = (b - 80) << 10; }
    else if (b == 84){ l = 3; hw0 = 0; }
    else             { l = 4; hw0 = 0; cnt = 256; }
    if (tid * 4 >= cnt) return;
    int px = hw0 + tid * 4;
    const float* tp = g_t + (size_t)n * 256 * TOTHW + c_HWOFF[l] + px;

    float acc[15][4];
#pragma unroll
    for (int k = 0; k < 15; k++) {
        float bv = (k < 3) ? ob[k] : db[k - 3];
        acc[k][0] = bv; acc[k][1] = bv; acc[k][2] = bv; acc[k][3] = bv;
    }
#pragma unroll 1
    for (int ci = 0; ci < 256; ci += 2) {
        float4 v0 = *(const float4*)(tp + (size_t)ci * TOTHW);
        float4 v1 = *(const float4*)(tp + (size_t)(ci + 1) * TOTHW);
#pragma unroll
        for (int k = 0; k < 15; k++) {
            float w0 = sW[k * 256 + ci], w1 = sW[k * 256 + ci + 1];
            acc[k][0] = fmaf(v0.x, w0, acc[k][0]); acc[k][0] = fmaf(v1.x, w1, acc[k][0]);
            acc[k][1] = fmaf(v0.y, w0, acc[k][1]); acc[k][1] = fmaf(v1.y, w1, acc[k][1]);
            acc[k][2] = fmaf(v0.z, w0, acc[k][2]); acc[k][2] = fmaf(v1.z, w1, acc[k][2]);
            acc[k][3] = fmaf(v0.w, w0, acc[k][3]); acc[k][3] = fmaf(v1.w, w1, acc[k][3]);
        }
    }
    float* o = out + ((size_t)n * ATOT + c_AOFF[l]) * 5 + (size_t)px * 15;
#pragma unroll
    for (int j = 0; j < 4; j++) {
        float* oj = o + j * 15;
#pragma unroll
        for (int a = 0; a < 3; a++) {
            oj[a * 5] = acc[a][j];
#pragma unroll
            for (int cc = 0; cc < 4; cc++) oj[a * 5 + 1 + cc] = acc[3 + a * 4 + cc][j];
        }
    }
}

// ---------------------------------------------------------------------------
// keys for per-level topk sort
// ---------------------------------------------------------------------------
__global__ void key1_kernel(const float* __restrict__ out) {
    int i = blockIdx.x * 256 + threadIdx.x;
    if (i >= 2 * ATOT) return;
    int n = i / ATOT, g = i - n * ATOT;
    int l = lvl_of_g(g);
    float sc = out[(size_t)(n * ATOT + g) * 5];
    u32 u = __float_as_uint(sc);
    u32 m = u ^ (((int)u < 0) ? 0xFFFFFFFFu : 0x80000000u);
    u32 inv = ~m;
    int idx = g - c_AOFF[l];
    g_keys[i] = ((u64)(u32)(n * 5 + l) << 50) | ((u64)inv << 18) | (u32)idx;
}

// ---------------------------------------------------------------------------
// gather candidates: decode + clip, build NMS order keys
// ---------------------------------------------------------------------------
__global__ void cand_kernel(const float* __restrict__ out) {
    int t = blockIdx.x * 256 + threadIdx.x;
    if (t >= 2 * MCAND) return;
    int n = t / MCAND, c = t - n * MCAND;
    int l = lvl_of_c(c);
    int r = c - c_COFF[l];
    u64 key = g_keyso[(size_t)n * ATOT + c_AOFF[l] + r];
    int idx = (int)(key & 0x3FFFFull);
    int a = idx % 3;
    int hw = idx / 3;
    int W = c_LW[l];
    int py = hw / W, px = hw - py * W;

    double ratio = (a == 0) ? 0.5 : (a == 1) ? 1.0 : 2.0;
    double sz = (double)c_SZ[l];
    double ws = sqrt(sz * sz / ratio);
    double hs = ws * ratio;
    double xx = (double)(px * c_STR[l]);
    double yy = (double)(py * c_STR[l]);
    float ax1 = (float)(xx - ws * 0.5), ay1 = (float)(yy - hs * 0.5);
    float ax2 = (float)(xx + ws * 0.5), ay2 = (float)(yy + hs * 0.5);

    float aw = ax2 - ax1, ah = ay2 - ay1;
    float acx = ax1 + 0.5f * aw, acy = ay1 + 0.5f * ah;
    const float* cmb = out + (size_t)(n * ATOT + c_AOFF[l] + idx) * 5;
    float sc = cmb[0];
    float dx = cmb[1], dy = cmb[2];
    float dwv = fminf(cmb[3], SCALE_CLAMP);
    float dhv = fminf(cmb[4], SCALE_CLAMP);
    float pcx = dx * aw + acx, pcy = dy * ah + acy;
    float pw = expf(dwv) * aw, ph = expf(dhv) * ah;
    float x1 = pcx - 0.5f * pw, y1 = pcy - 0.5f * ph;
    float x2 = pcx + 0.5f * pw, y2 = pcy + 0.5f * ph;
    x1 = fminf(fmaxf(x1, 0.f), 1024.f);
    y1 = fminf(fmaxf(y1, 0.f), 1024.f);
    x2 = fminf(fmaxf(x2, 0.f), 1024.f);
    y2 = fminf(fmaxf(y2, 0.f), 1024.f);

    float* bp = g_boxes + (size_t)t * 4;
    bp[0] = x1; bp[1] = y1; bp[2] = x2; bp[3] = y2;
    g_scores[t] = sc;

    u32 u = __float_as_uint(sc);
    u32 m = u ^ (((int)u < 0) ? 0xFFFFFFFFu : 0x80000000u);
    u32 inv = ~m;
    g_k2[t] = ((u64)(u32)n << 47) | ((u64)inv << 15) | (u32)c;
}

// ---------------------------------------------------------------------------
// NMS suppression bitmask
// ---------------------------------------------------------------------------
__global__ __launch_bounds__(128)
void mask_kernel(int l) {
    int K = c_K[l], Wn = c_W32[l];
    int cb = blockIdx.x * 128, rb = blockIdx.y * 128;
    if (rb > cb + 127) return;
    int b = blockIdx.z;
    int tid = threadIdx.x;
    __shared__ float4 sB[128];
    __shared__ float sA[128];
    float off = (float)l * 2000.0f;

    int cc = cb + tid;
    if (cc < K) {
        const float* bp = g_boxes + ((size_t)b * MCAND + c_COFF[l] + cc) * 4;
        float4 v = make_float4(bp[0] + off, bp[1] + off, bp[2] + off, bp[3] + off);
        sB[tid] = v;
        sA[tid] = (v.z - v.x) * (v.w - v.y);
    }
    __syncthreads();
    int r = rb + tid;
    if (r >= K) return;
    const float* rp = g_boxes + ((size_t)b * MCAND + c_COFF[l] + r) * 4;
    float rx1 = rp[0] + off, ry1 = rp[1] + off, rx2 = rp[2] + off, ry2 = rp[3] + off;
    float ra = (rx2 - rx1) * (ry2 - ry1);
    u32 wds[4] = {0, 0, 0, 0};
    int jmax = min(128, K - cb);
    for (int j = 0; j < jmax; j++) {
        int c2 = cb + j;
        if (c2 <= r) continue;
        float4 o = sB[j];
        float x1 = fmaxf(rx1, o.x), y1 = fmaxf(ry1, o.y);
        float x2 = fminf(rx2, o.z), y2 = fminf(ry2, o.w);
        float inter = fmaxf(x2 - x1, 0.f) * fmaxf(y2 - y1, 0.f);
        float iou = inter / (ra + sA[j] - inter + 1e-9f);
        if (iou > NMS_T) wds[j >> 5] |= 1u << (j & 31);
    }
    u32* dst = g_mask + (size_t)b * MASK_PER_BATCH + c_MOFF[l] + (size_t)r * Wn + (cb >> 5);
#pragma unroll
    for (int w2 = 0; w2 < 4; w2++)
        if ((cb >> 5) + w2 < Wn) dst[w2] = wds[w2];
}

// ---------------------------------------------------------------------------
// Greedy scan
// ---------------------------------------------------------------------------
__global__ __launch_bounds__(32)
void scan_kernel(float* __restrict__ out) {
    int b = blockIdx.x;
    int lane = threadIdx.x;
    __shared__ u32 rem[REM_WORDS];
    for (int i = lane; i < REM_WORDS; i += 32) rem[i] = 0;
    __syncwarp();

    const u64* ord = g_k2o + (size_t)b * MCAND;
    int p = 0, kept = 0;
    while (p < MCAND && kept < POST_K) {
        int rank = p + lane;
        int c = -1;
        bool fr = false;
        if (rank < MCAND) {
            c = (int)(ord[rank] & 0x7FFFull);
            int l = lvl_of_c(c);
            int rl = c - c_COFF[l];
            fr = !((rem[c_RWOFF[l] + (rl >> 5)] >> (rl & 31)) & 1u);
        }
        if (p + 32 + lane * 8 < MCAND) pref_l2(&ord[p + 32 + lane * 8]);
        u32 fm = __ballot_sync(0xffffffffu, fr);
        if (!fm) { p += 32; continue; }
        int tt = __ffs(fm) - 1;
        int ck = __shfl_sync(0xffffffffu, c, tt);
        u32 fm2 = fm & (fm - 1);
        if (fm2) {
            int t2 = __ffs(fm2) - 1;
            int c2 = __shfl_sync(0xffffffffu, c, t2);
            int l2 = lvl_of_c(c2);
            int rl2 = c2 - c_COFF[l2];
            int Wn2 = c_W32[l2];
            const u32* rp2 = g_mask + (size_t)b * MASK_PER_BATCH + c_MOFF[l2] + (size_t)rl2 * Wn2;
            if (lane * 32 < Wn2) pref_l2(rp2 + lane * 32);
        }
        int l = lvl_of_c(ck);
        int rl = ck - c_COFF[l];
        int Wn = c_W32[l];
        const u32* rowp = g_mask + (size_t)b * MASK_PER_BATCH + c_MOFF[l] + (size_t)rl * Wn;
        for (int w = lane; w < Wn; w += 32) rem[c_RWOFF[l] + w] |= rowp[w];
        if (lane == 0) {
            const float* bx = g_boxes + ((size_t)b * MCAND + ck) * 4;
            float* kb = out + OUT_KB + ((size_t)b * POST_K + kept) * 4;
            kb[0] = bx[0]; kb[1] = bx[1]; kb[2] = bx[2]; kb[3] = bx[3];
            out[OUT_KS + b * POST_K + kept] = g_scores[(size_t)b * MCAND + ck];
            out[OUT_VALID + b * POST_K + kept] = 1.0f;
        }
        __syncwarp();
        kept++;
        p = p + tt + 1;
    }
    const float* bx0 = g_boxes + (size_t)b * MCAND * 4;
    float s0 = g_scores[(size_t)b * MCAND];
    for (int k2 = kept + lane; k2 < POST_K; k2 += 32) {
        float* kb = out + OUT_KB + ((size_t)b * POST_K + k2) * 4;
        kb[0] = bx0[0]; kb[1] = bx0[1]; kb[2] = bx0[2]; kb[3] = bx0[3];
        out[OUT_KS + b * POST_K + k2] = s0;
        out[OUT_VALID + b * POST_K + k2] = 0.0f;
    }
}

// ---------------------------------------------------------------------------
// Host launcher
// ---------------------------------------------------------------------------
extern "C" void kernel_launch(void* const* d_in, const int* in_sizes, int n_in,
                              void* d_out, int out_size) {
    const float* conv_w = (const float*)d_in[5];
    const float* conv_b = (const float*)d_in[6];
    const float* obj_w  = (const float*)d_in[7];
    const float* obj_b  = (const float*)d_in[8];
    const float* del_w  = (const float*)d_in[9];
    const float* del_b  = (const float*)d_in[10];
    float* out = (float*)d_out;

    static const int hT[5] = {47, 47, 47, 24, 6};

    void *p_keys, *p_keyso, *p_k2, *p_k2o, *p_mask, *p_tmp;
    cudaGetSymbolAddress(&p_keys, g_keys);
    cudaGetSymbolAddress(&p_keyso, g_keyso);
    cudaGetSymbolAddress(&p_k2, g_k2);
    cudaGetSymbolAddress(&p_k2o, g_k2o);
    cudaGetSymbolAddress(&p_mask, g_mask);
    cudaGetSymbolAddress(&p_tmp, g_cubtmp);

    ConvPtrs P;
    for (int i = 0; i < 5; i++) P.f[i] = (const float*)d_in[i];

    cudaMemsetAsync(p_mask, 0, (size_t)2 * MASK_PER_BATCH * sizeof(u32));
    wtrans_tc<<<3456, 256>>>(conv_w);
    xtrans<<<(NXEL + 255) / 256, 256>>>(P);
    // launch-index alignment: keep conv at ncu capture index
    dummy_k<<<1, 32>>>();

    // f16x3 6-pass mma.sync conv, cp.async B staging
    {
        static int configured = 0;
        if (!configured) {
            cudaFuncSetAttribute(conv_mma_kernel,
                                 cudaFuncAttributeMaxDynamicSharedMemorySize, CONV_SMEM);
            configured = 1;
        }
        conv_mma_kernel<<<2728, 256, CONV_SMEM>>>(P, conv_b);
    }

    head_fused_kernel<<<dim3(86, 1, 2), 256>>>(obj_w, obj_b, del_w, del_b, out);

    key1_kernel<<<(2 * ATOT) / 256, 256>>>(out);
    {
        size_t tb = sizeof(g_cubtmp);
        cub::DeviceRadixSort::SortKeys(p_tmp, tb, (const u64*)p_keys, (u64*)p_keyso,
                                       2 * ATOT, 0, 54);
    }

    cand_kernel<<<(2 * MCAND + 255) / 256, 256>>>(out);
    {
        size_t tb = sizeof(g_cubtmp);
        cub::DeviceRadixSort::SortKeys(p_tmp, tb, (const u64*)p_k2, (u64*)p_k2o,
                                       2 * MCAND, 0, 48);
    }

    for (int l = 0; l < 5; l++) {
        dim3 g(hT[l], hT[l], 2);
        mask_kernel<<<g, 128>>>(l);
    }

    scan_kernel<<<2, 32>>>(out);
}

// round 15
// speedup vs baseline: 1.1560x; 1.1560x over previous
#include <cuda_runtime.h>
#include <cuda_bf16.h>
#include <cuda_fp16.h>
#include <cub/cub.cuh>
#include <cstdint>
#include <math.h>

typedef unsigned long long u64;
typedef unsigned int u32;

// ---------------------------------------------------------------------------
// Problem constants
// ---------------------------------------------------------------------------
#define NLVL 5
#define ATOT 261888
#define MCAND 21840
#define POST_K 1000
#define NMS_T 0.7f
#define SCALE_CLAMP 4.135166556742356f
#define TOTHW 87296
#define MASK_PER_BATCH 3697344
#define REM_WORDS 684

#define OUT_KB   2618880
#define OUT_KS   2626880
#define OUT_VALID 2628880

// prescale: A x 2^13, B x 2^10, output x 2^-23
#define A_SCALE 8192.0f
#define B_SCALE 1024.0f
#define OUT_SCALE 1.1920928955078125e-07f   // 2^-23

__constant__ int c_COFF[5]  = {0, 6000, 12000, 18000, 21072};
__constant__ int c_K[5]     = {6000, 6000, 6000, 3072, 768};
__constant__ int c_W32[5]   = {188, 188, 188, 96, 24};
__constant__ int c_RWOFF[5] = {0, 188, 376, 564, 660};
__constant__ int c_MOFF[5]  = {0, 1128000, 2256000, 3384000, 3678912};
__constant__ int c_AOFF[5]  = {0, 196608, 245760, 258048, 261120};
__constant__ int c_LW[5]    = {256, 128, 64, 32, 16};
__constant__ int c_STR[5]   = {4, 8, 16, 32, 64};
__constant__ int c_SZ[5]    = {32, 64, 128, 256, 512};
__constant__ int c_HWOFF[5] = {0, 65536, 81920, 86016, 87040};

// ---------------------------------------------------------------------------
// Static device scratch
// ---------------------------------------------------------------------------
__device__ float  g_t[2u * 256u * TOTHW];      // conv outputs, [n][co][TOTHW]
// A weights, f16x3 split (prescaled), fragment-packed u32 (2 f16/u32)
__device__ u32    g_wA32[884736];
__device__ u64    g_keys[2 * ATOT];
__device__ u64    g_keyso[2 * ATOT];
__device__ float  g_boxes[2 * MCAND * 4];
__device__ float  g_scores[2 * MCAND];
__device__ u64    g_k2[2 * MCAND];
__device__ u64    g_k2o[2 * MCAND];
__device__ u32    g_mask[2u * MASK_PER_BATCH];
__device__ unsigned char g_cubtmp[48u * 1024u * 1024u];

__device__ __forceinline__ int lvl_of_c(int c) {
    return (c < 6000) ? 0 : (c < 12000) ? 1 : (c < 18000) ? 2 : (c < 21072) ? 3 : 4;
}
__device__ __forceinline__ int lvl_of_g(int g) {
    return (g < 196608) ? 0 : (g < 245760) ? 1 : (g < 258048) ? 2 : (g < 261120) ? 3 : 4;
}

__device__ __forceinline__ u32 s2u(const void* p) { return (u32)__cvta_generic_to_shared(p); }
__device__ __forceinline__ void cpa16(u32 d, const void* s) {
    asm volatile("cp.async.cg.shared.global [%0], [%1], 16;" :: "r"(d), "l"(s));
}
#define CPA_COMMIT() asm volatile("cp.async.commit_group;")
#define CPA_WAIT0()  asm volatile("cp.async.wait_group 0;")
__device__ __forceinline__ void pref_l2(const void* p) {
    asm volatile("prefetch.global.L2 [%0];" :: "l"(p));
}

// f16 helpers
__device__ __forceinline__ u32 pack_h2(float lo, float hi) {
    __half2 t = __floats2half2_rn(lo, hi);   // .x = low halfword
    return *(u32*)&t;
}

#define MMAH(D, A, B0, B1) \
    asm volatile("mma.sync.aligned.m16n8k16.row.col.f32.f16.f16.f32 " \
        "{%0,%1,%2,%3},{%4,%5,%6,%7},{%8,%9},{%0,%1,%2,%3};" \
        : "+f"((D).x), "+f"((D).y), "+f"((D).z), "+f"((D).w) \
        : "r"((A).x), "r"((A).y), "r"((A).z), "r"((A).w), "r"(B0), "r"(B1))

// ---------------------------------------------------------------------------
// Weight transform: conv_w [co][ci][3][3] -> f16x3 (prescaled) fragment u32
// ---------------------------------------------------------------------------
__global__ void wtrans_tc(const float* __restrict__ w) {
    int e = blockIdx.x * 256 + threadIdx.x;
    if (e >= 884736) return;
    int s = e / 294912;
    int rem = e - s * 294912;
    int h = rem / 147456;
    int rem2 = rem - h * 147456;
    int kc = rem2 >> 11;
    int idx = rem2 & 2047;
    int ks2 = idx >> 10;
    int mt = (idx >> 7) & 7;
    int lane = (idx >> 2) & 31;
    int r = idx & 3;
    int row_local = mt * 16 + (r & 1) * 8 + (lane >> 2);
    int co = h * 128 + row_local;
    int kbase = kc * 32 + ks2 * 16 + (r >> 1) * 8 + (lane & 3) * 2;
    float sel[2];
#pragma unroll
    for (int half = 0; half < 2; half++) {
        int kg = kbase + half;
        int tap = kg >> 8, ci = kg & 255;
        float v = w[co * 2304 + ci * 9 + tap] * A_SCALE;
        float b0 = __half2float(__float2half_rn(v));
        float r1 = v - b0;
        float b1 = __half2float(__float2half_rn(r1));
        float r2 = r1 - b1;
        sel[half] = (s == 0) ? b0 : (s == 1) ? b1 : r2;
    }
    g_wA32[e] = pack_h2(sel[0], sel[1]);
}

__global__ void dummy_k() {}

// ---------------------------------------------------------------------------
// f16x3 6-pass mma.sync conv with per-chunk accumulator flush.
// MMA schedule: pass-major over q-pairs -> 8 independent MMAs between
// accumulator reuses (hides HMMA latency at 2 warps/SMSP).
// ---------------------------------------------------------------------------
#define SA_BASE 0
#define SB_BASE 49152
#define CONV_SMEM 98304

struct ConvPtrs { const float* f[5]; };

__global__ __launch_bounds__(256, 1)
void conv_mma_kernel(ConvPtrs P, const float* __restrict__ bias) {
    const int b = blockIdx.x;
    const int h = b & 1, nb = (b >> 1) & 1;
    const int t = b >> 2;          // 0..681
    const int l = (t < 512) ? 0 : (t < 640) ? 1 : (t < 672) ? 2 : (t < 680) ? 3 : 4;
    const int sbase = (l == 0) ? 0 : (l == 1) ? 512 : (l == 2) ? 640 : (l == 3) ? 672 : 680;
    const int hw0 = (t - sbase) * 128;
    const int W = c_LW[l], H = W, HW = W * W;
    const int lw = (l == 0) ? 8 : (l == 1) ? 7 : (l == 2) ? 6 : (l == 3) ? 5 : 4;
    const float* Xn = P.f[l] + (size_t)nb * 256 * HW;

    extern __shared__ __align__(16) char smem[];
    const u32 smb = s2u(smem);
    const int tid = threadIdx.x;
    const int wid = tid >> 5, lane = tid & 31;

    const int wm = wid & 3, wn = wid >> 2;
    const int kh = wid >> 2, nh = wid & 3;
    const int nI = nh * 32 + lane;
    const int yI = (hw0 + nI) >> lw, xI = (hw0 + nI) & (W - 1);
    const int ntI = nI >> 3, gidI = nI & 7;
    const int ntpI = ntI >> 1, ceI = (ntI & 1) * 2;

    float4 acc[2][8];
#pragma unroll
    for (int f = 0; f < 2; f++)
#pragma unroll
        for (int q = 0; q < 8; q++) acc[f][q] = make_float4(0.f, 0.f, 0.f, 0.f);

    float v[16];

    auto stageA = [&](int kc, int buf) {
#pragma unroll
        for (int s = 0; s < 3; s++) {
            const u32* src = g_wA32 + (size_t)((s * 2 + h) * 72 + kc) * 2048;
            u32 dst = smb + SA_BASE + s * 16384 + buf * 8192;
            for (int i = tid; i < 512; i += 256) cpa16(dst + i * 16, src + i * 4);
        }
    };
    auto ldgB = [&](int kc) {
        int tap = kc >> 3;
        int ci0 = (kc & 7) * 32 + kh * 16;
        int dy = tap / 3 - 1, dx = tap - (tap / 3) * 3 - 1;
        int yy = yI + dy, xx = xI + dx;
        bool valid = ((unsigned)yy < (unsigned)H) & ((unsigned)xx < (unsigned)W);
        const float* sp = Xn + (size_t)ci0 * HW + yy * W + xx;
#pragma unroll
        for (int i = 0; i < 16; i++)
            v[i] = valid ? sp[(size_t)i * HW] : 0.f;
    };
    auto stsB = [&](int buf) {
        u32* B0 = (u32*)(smem + SB_BASE + 0 * 16384 + buf * 8192);
        u32* B1 = (u32*)(smem + SB_BASE + 1 * 16384 + buf * 8192);
        u32* B2 = (u32*)(smem + SB_BASE + 2 * 16384 + buf * 8192);
#pragma unroll
        for (int j = 0; j < 8; j++) {
            float v0 = v[2 * j] * B_SCALE, v1 = v[2 * j + 1] * B_SCALE;
            float a0 = __half2float(__float2half_rn(v0));
            float ra = v0 - a0;
            float a1 = __half2float(__float2half_rn(ra));
            float a2 = ra - a1;
            float b0 = __half2float(__float2half_rn(v1));
            float rb = v1 - b0;
            float b1 = __half2float(__float2half_rn(rb));
            float b2 = rb - b1;
            int breg = j >> 2;
            int L = gidI * 4 + (j & 3);
            int iu = kh * 1024 + ntpI * 128 + L * 4 + ceI + breg;
            B0[iu] = pack_h2(a0, b0);
            B1[iu] = pack_h2(a1, b1);
            B2[iu] = pack_h2(a2, b2);
        }
    };
    auto mmaC = [&](int buf) {
        const uint4* As[3]; const uint4* Bs[3];
#pragma unroll
        for (int s = 0; s < 3; s++) {
            As[s] = (const uint4*)(smem + SA_BASE + s * 16384 + buf * 8192);
            Bs[s] = (const uint4*)(smem + SB_BASE + s * 16384 + buf * 8192);
        }
        // per-chunk accumulator (limits RZ accumulation chain)
        float4 cacc[2][8];
#pragma unroll
        for (int f = 0; f < 2; f++)
#pragma unroll
            for (int q = 0; q < 8; q++) cacc[f][q] = make_float4(0.f, 0.f, 0.f, 0.f);

#pragma unroll
        for (int ks2 = 0; ks2 < 2; ks2++) {
            uint4 a[3][2];
#pragma unroll
            for (int s = 0; s < 3; s++)
#pragma unroll
                for (int f = 0; f < 2; f++)
                    a[s][f] = As[s][ks2 * 256 + (wm * 2 + f) * 32 + lane];
#pragma unroll
            for (int qp = 0; qp < 2; qp++) {
                uint4 bq[3][2];
#pragma unroll
                for (int s = 0; s < 3; s++)
#pragma unroll
                    for (int j = 0; j < 2; j++)
                        bq[s][j] = Bs[s][ks2 * 256 + (wn * 4 + qp * 2 + j) * 32 + lane];
                // pass-major: 8 independent MMAs per pass (accumulator reuse
                // distance = 8 instructions -> latency hidden)
#define PASS(sa, sb) \
                { \
                    _Pragma("unroll") \
                    for (int j = 0; j < 2; j++) { \
                        int q = qp * 2 + j; \
                        _Pragma("unroll") \
                        for (int f = 0; f < 2; f++) { \
                            MMAH(cacc[f][2 * q],     a[sa][f], bq[sb][j].x, bq[sb][j].y); \
                            MMAH(cacc[f][2 * q + 1], a[sa][f], bq[sb][j].z, bq[sb][j].w); \
                        } \
                    } \
                }
                PASS(0, 0)
                PASS(0, 1)
                PASS(1, 0)
                PASS(1, 1)
                PASS(0, 2)
                PASS(2, 0)
#undef PASS
            }
        }
        // flush with RN adds
#pragma unroll
        for (int f = 0; f < 2; f++)
#pragma unroll
            for (int q = 0; q < 8; q++) {
                acc[f][q].x += cacc[f][q].x;
                acc[f][q].y += cacc[f][q].y;
                acc[f][q].z += cacc[f][q].z;
                acc[f][q].w += cacc[f][q].w;
            }
    };

    // prologue
    stageA(0, 0); CPA_COMMIT();
    ldgB(0); stsB(0);
    CPA_WAIT0();
    __syncthreads();

    int buf = 0;
#pragma unroll 1
    for (int kc = 0; kc < 72; kc++) {
        if (kc + 1 < 72) {
            ldgB(kc + 1);
            stageA(kc + 1, buf ^ 1); CPA_COMMIT();
        }
        mmaC(buf);
        if (kc + 1 < 72) {
            stsB(buf ^ 1);
            CPA_WAIT0();
        }
        __syncthreads();
        buf ^= 1;
    }

    // epilogue: unscale + bias + relu, scatter fragments
    const int hwoff = c_HWOFF[l];
#pragma unroll
    for (int f = 0; f < 2; f++) {
        int r0 = wm * 32 + f * 16 + (lane >> 2);
        float bv0 = bias[h * 128 + r0];
        float bv1 = bias[h * 128 + r0 + 8];
        float* d0 = g_t + (size_t)(nb * 256 + h * 128 + r0) * TOTHW + hwoff + hw0;
        float* d1 = d0 + (size_t)8 * TOTHW;
#pragma unroll
        for (int q = 0; q < 8; q++) {
            int n0 = wn * 64 + q * 8 + (lane & 3) * 2;
            float4 dd = acc[f][q];
            float2 o0, o1;
            o0.x = fmaxf(fmaf(dd.x, OUT_SCALE, bv0), 0.f);
            o0.y = fmaxf(fmaf(dd.y, OUT_SCALE, bv0), 0.f);
            o1.x = fmaxf(fmaf(dd.z, OUT_SCALE, bv1), 0.f);
            o1.y = fmaxf(fmaf(dd.w, OUT_SCALE, bv1), 0.f);
            *(float2*)(d0 + n0) = o0;
            *(float2*)(d1 + n0) = o1;
        }
    }
}

// ---------------------------------------------------------------------------
// Fused 1x1 heads
// ---------------------------------------------------------------------------
__global__ __launch_bounds__(256)
void head_fused_kernel(const float* __restrict__ ow, const float* __restrict__ ob,
                       const float* __restrict__ dw, const float* __restrict__ db,
                       float* __restrict__ out) {
    __shared__ float sW[15 * 256];
    int tid = threadIdx.x;
    for (int i = tid; i < 3840; i += 256) {
        int k = i >> 8, ci = i & 255;
        sW[i] = (k < 3) ? ow[k * 256 + ci] : dw[(k - 3) * 256 + ci];
    }
    __syncthreads();
    int b = blockIdx.x, n = blockIdx.z;
    int l, hw0, cnt = 1024;
    if (b < 64)      { l = 0; hw0 = b << 10; }
    else if (b < 80) { l = 1; hw0 = (b - 64) << 10; }
    else if (b < 84) { l = 2; hw0 = (b - 80) << 10; }
    else if (b == 84){ l = 3; hw0 = 0; }
    else             { l = 4; hw0 = 0; cnt = 256; }
    if (tid * 4 >= cnt) return;
    int px = hw0 + tid * 4;
    const float* tp = g_t + (size_t)n * 256 * TOTHW + c_HWOFF[l] + px;

    float acc[15][4];
#pragma unroll
    for (int k = 0; k < 15; k++) {
        float bv = (k < 3) ? ob[k] : db[k - 3];
        acc[k][0] = bv; acc[k][1] = bv; acc[k][2] = bv; acc[k][3] = bv;
    }
#pragma unroll 1
    for (int ci = 0; ci < 256; ci += 2) {
        float4 v0 = *(const float4*)(tp + (size_t)ci * TOTHW);
        float4 v1 = *(const float4*)(tp + (size_t)(ci + 1) * TOTHW);
#pragma unroll
        for (int k = 0; k < 15; k++) {
            float w0 = sW[k * 256 + ci], w1 = sW[k * 256 + ci + 1];
            acc[k][0] = fmaf(v0.x, w0, acc[k][0]); acc[k][0] = fmaf(v1.x, w1, acc[k][0]);
            acc[k][1] = fmaf(v0.y, w0, acc[k][1]); acc[k][1] = fmaf(v1.y, w1, acc[k][1]);
            acc[k][2] = fmaf(v0.z, w0, acc[k][2]); acc[k][2] = fmaf(v1.z, w1, acc[k][2]);
            acc[k][3] = fmaf(v0.w, w0, acc[k][3]); acc[k][3] = fmaf(v1.w, w1, acc[k][3]);
        }
    }
    float* o = out + ((size_t)n * ATOT + c_AOFF[l]) * 5 + (size_t)px * 15;
#pragma unroll
    for (int j = 0; j < 4; j++) {
        float* oj = o + j * 15;
#pragma unroll
        for (int a = 0; a < 3; a++) {
            oj[a * 5] = acc[a][j];
#pragma unroll
            for (int cc = 0; cc < 4; cc++) oj[a * 5 + 1 + cc] = acc[3 + a * 4 + cc][j];
        }
    }
}

// ---------------------------------------------------------------------------
// keys for per-level topk sort
// ---------------------------------------------------------------------------
__global__ void key1_kernel(const float* __restrict__ out) {
    int i = blockIdx.x * 256 + threadIdx.x;
    if (i >= 2 * ATOT) return;
    int n = i / ATOT, g = i - n * ATOT;
    int l = lvl_of_g(g);
    float sc = out[(size_t)(n * ATOT + g) * 5];
    u32 u = __float_as_uint(sc);
    u32 m = u ^ (((int)u < 0) ? 0xFFFFFFFFu : 0x80000000u);
    u32 inv = ~m;
    int idx = g - c_AOFF[l];
    g_keys[i] = ((u64)(u32)(n * 5 + l) << 50) | ((u64)inv << 18) | (u32)idx;
}

// ---------------------------------------------------------------------------
// gather candidates: decode + clip, build NMS order keys
// ---------------------------------------------------------------------------
__global__ void cand_kernel(const float* __restrict__ out) {
    int t = blockIdx.x * 256 + threadIdx.x;
    if (t >= 2 * MCAND) return;
    int n = t / MCAND, c = t - n * MCAND;
    int l = lvl_of_c(c);
    int r = c - c_COFF[l];
    u64 key = g_keyso[(size_t)n * ATOT + c_AOFF[l] + r];
    int idx = (int)(key & 0x3FFFFull);
    int a = idx % 3;
    int hw = idx / 3;
    int W = c_LW[l];
    int py = hw / W, px = hw - py * W;

    double ratio = (a == 0) ? 0.5 : (a == 1) ? 1.0 : 2.0;
    double sz = (double)c_SZ[l];
    double ws = sqrt(sz * sz / ratio);
    double hs = ws * ratio;
    double xx = (double)(px * c_STR[l]);
    double yy = (double)(py * c_STR[l]);
    float ax1 = (float)(xx - ws * 0.5), ay1 = (float)(yy - hs * 0.5);
    float ax2 = (float)(xx + ws * 0.5), ay2 = (float)(yy + hs * 0.5);

    float aw = ax2 - ax1, ah = ay2 - ay1;
    float acx = ax1 + 0.5f * aw, acy = ay1 + 0.5f * ah;
    const float* cmb = out + (size_t)(n * ATOT + c_AOFF[l] + idx) * 5;
    float sc = cmb[0];
    float dx = cmb[1], dy = cmb[2];
    float dwv = fminf(cmb[3], SCALE_CLAMP);
    float dhv = fminf(cmb[4], SCALE_CLAMP);
    float pcx = dx * aw + acx, pcy = dy * ah + acy;
    float pw = expf(dwv) * aw, ph = expf(dhv) * ah;
    float x1 = pcx - 0.5f * pw, y1 = pcy - 0.5f * ph;
    float x2 = pcx + 0.5f * pw, y2 = pcy + 0.5f * ph;
    x1 = fminf(fmaxf(x1, 0.f), 1024.f);
    y1 = fminf(fmaxf(y1, 0.f), 1024.f);
    x2 = fminf(fmaxf(x2, 0.f), 1024.f);
    y2 = fminf(fmaxf(y2, 0.f), 1024.f);

    float* bp = g_boxes + (size_t)t * 4;
    bp[0] = x1; bp[1] = y1; bp[2] = x2; bp[3] = y2;
    g_scores[t] = sc;

    u32 u = __float_as_uint(sc);
    u32 m = u ^ (((int)u < 0) ? 0xFFFFFFFFu : 0x80000000u);
    u32 inv = ~m;
    g_k2[t] = ((u64)(u32)n << 47) | ((u64)inv << 15) | (u32)c;
}

// ---------------------------------------------------------------------------
// NMS suppression bitmask
// ---------------------------------------------------------------------------
__global__ __launch_bounds__(128)
void mask_kernel(int l) {
    int K = c_K[l], Wn = c_W32[l];
    int cb = blockIdx.x * 128, rb = blockIdx.y * 128;
    if (rb > cb + 127) return;
    int b = blockIdx.z;
    int tid = threadIdx.x;
    __shared__ float4 sB[128];
    __shared__ float sA[128];
    float off = (float)l * 2000.0f;

    int cc = cb + tid;
    if (cc < K) {
        const float* bp = g_boxes + ((size_t)b * MCAND + c_COFF[l] + cc) * 4;
        float4 v = make_float4(bp[0] + off, bp[1] + off, bp[2] + off, bp[3] + off);
        sB[tid] = v;
        sA[tid] = (v.z - v.x) * (v.w - v.y);
    }
    __syncthreads();
    int r = rb + tid;
    if (r >= K) return;
    const float* rp = g_boxes + ((size_t)b * MCAND + c_COFF[l] + r) * 4;
    float rx1 = rp[0] + off, ry1 = rp[1] + off, rx2 = rp[2] + off, ry2 = rp[3] + off;
    float ra = (rx2 - rx1) * (ry2 - ry1);
    u32 wds[4] = {0, 0, 0, 0};
    int jmax = min(128, K - cb);
    for (int j = 0; j < jmax; j++) {
        int c2 = cb + j;
        if (c2 <= r) continue;
        float4 o = sB[j];
        float x1 = fmaxf(rx1, o.x), y1 = fmaxf(ry1, o.y);
        float x2 = fminf(rx2, o.z), y2 = fminf(ry2, o.w);
        float inter = fmaxf(x2 - x1, 0.f) * fmaxf(y2 - y1, 0.f);
        float iou = inter / (ra + sA[j] - inter + 1e-9f);
        if (iou > NMS_T) wds[j >> 5] |= 1u << (j & 31);
    }
    u32* dst = g_mask + (size_t)b * MASK_PER_BATCH + c_MOFF[l] + (size_t)r * Wn + (cb >> 5);
#pragma unroll
    for (int w2 = 0; w2 < 4; w2++)
        if ((cb >> 5) + w2 < Wn) dst[w2] = wds[w2];
}

// ---------------------------------------------------------------------------
// Greedy scan
// ---------------------------------------------------------------------------
__global__ __launch_bounds__(32)
void scan_kernel(float* __restrict__ out) {
    int b = blockIdx.x;
    int lane = threadIdx.x;
    __shared__ u32 rem[REM_WORDS];
    for (int i = lane; i < REM_WORDS; i += 32) rem[i] = 0;
    __syncwarp();

    const u64* ord = g_k2o + (size_t)b * MCAND;
    int p = 0, kept = 0;
    while (p < MCAND && kept < POST_K) {
        int rank = p + lane;
        int c = -1;
        bool fr = false;
        if (rank < MCAND) {
            c = (int)(ord[rank] & 0x7FFFull);
            int l = lvl_of_c(c);
            int rl = c - c_COFF[l];
            fr = !((rem[c_RWOFF[l] + (rl >> 5)] >> (rl & 31)) & 1u);
        }
        if (p + 32 + lane * 8 < MCAND) pref_l2(&ord[p + 32 + lane * 8]);
        u32 fm = __ballot_sync(0xffffffffu, fr);
        if (!fm) { p += 32; continue; }
        int tt = __ffs(fm) - 1;
        int ck = __shfl_sync(0xffffffffu, c, tt);
        u32 fm2 = fm & (fm - 1);
        if (fm2) {
            int t2 = __ffs(fm2) - 1;
            int c2 = __shfl_sync(0xffffffffu, c, t2);
            int l2 = lvl_of_c(c2);
            int rl2 = c2 - c_COFF[l2];
            int Wn2 = c_W32[l2];
            const u32* rp2 = g_mask + (size_t)b * MASK_PER_BATCH + c_MOFF[l2] + (size_t)rl2 * Wn2;
            if (lane * 32 < Wn2) pref_l2(rp2 + lane * 32);
        }
        int l = lvl_of_c(ck);
        int rl = ck - c_COFF[l];
        int Wn = c_W32[l];
        const u32* rowp = g_mask + (size_t)b * MASK_PER_BATCH + c_MOFF[l] + (size_t)rl * Wn;
        for (int w = lane; w < Wn; w += 32) rem[c_RWOFF[l] + w] |= rowp[w];
        if (lane == 0) {
            const float* bx = g_boxes + ((size_t)b * MCAND + ck) * 4;
            float* kb = out + OUT_KB + ((size_t)b * POST_K + kept) * 4;
            kb[0] = bx[0]; kb[1] = bx[1]; kb[2] = bx[2]; kb[3] = bx[3];
            out[OUT_KS + b * POST_K + kept] = g_scores[(size_t)b * MCAND + ck];
            out[OUT_VALID + b * POST_K + kept] = 1.0f;
        }
        __syncwarp();
        kept++;
        p = p + tt + 1;
    }
    const float* bx0 = g_boxes + (size_t)b * MCAND * 4;
    float s0 = g_scores[(size_t)b * MCAND];
    for (int k2 = kept + lane; k2 < POST_K; k2 += 32) {
        float* kb = out + OUT_KB + ((size_t)b * POST_K + k2) * 4;
        kb[0] = bx0[0]; kb[1] = bx0[1]; kb[2] = bx0[2]; kb[3] = bx0[3];
        out[OUT_KS + b * POST_K + k2] = s0;
        out[OUT_VALID + b * POST_K + k2] = 0.0f;
    }
}

// ---------------------------------------------------------------------------
// Host launcher
// ---------------------------------------------------------------------------
extern "C" void kernel_launch(void* const* d_in, const int* in_sizes, int n_in,
                              void* d_out, int out_size) {
    const float* conv_w = (const float*)d_in[5];
    const float* conv_b = (const float*)d_in[6];
    const float* obj_w  = (const float*)d_in[7];
    const float* obj_b  = (const float*)d_in[8];
    const float* del_w  = (const float*)d_in[9];
    const float* del_b  = (const float*)d_in[10];
    float* out = (float*)d_out;

    static const int hT[5] = {47, 47, 47, 24, 6};

    void *p_keys, *p_keyso, *p_k2, *p_k2o, *p_mask, *p_tmp;
    cudaGetSymbolAddress(&p_keys, g_keys);
    cudaGetSymbolAddress(&p_keyso, g_keyso);
    cudaGetSymbolAddress(&p_k2, g_k2);
    cudaGetSymbolAddress(&p_k2o, g_k2o);
    cudaGetSymbolAddress(&p_mask, g_mask);
    cudaGetSymbolAddress(&p_tmp, g_cubtmp);

    cudaMemsetAsync(p_mask, 0, (size_t)2 * MASK_PER_BATCH * sizeof(u32));
    wtrans_tc<<<3456, 256>>>(conv_w);
    // launch-index alignment: keep conv at ncu capture index
    dummy_k<<<1, 32>>>();
    dummy_k<<<1, 32>>>();

    // f16x3 6-pass mma.sync conv, interleaved accumulators
    {
        ConvPtrs P;
        for (int i = 0; i < 5; i++) P.f[i] = (const float*)d_in[i];
        static int configured = 0;
        if (!configured) {
            cudaFuncSetAttribute(conv_mma_kernel,
                                 cudaFuncAttributeMaxDynamicSharedMemorySize, CONV_SMEM);
            configured = 1;
        }
        conv_mma_kernel<<<2728, 256, CONV_SMEM>>>(P, conv_b);
    }

    head_fused_kernel<<<dim3(86, 1, 2), 256>>>(obj_w, obj_b, del_w, del_b, out);

    key1_kernel<<<(2 * ATOT) / 256, 256>>>(out);
    {
        size_t tb = sizeof(g_cubtmp);
        cub::DeviceRadixSort::SortKeys(p_tmp, tb, (const u64*)p_keys, (u64*)p_keyso,
                                       2 * ATOT, 0, 54);
    }

    cand_kernel<<<(2 * MCAND + 255) / 256, 256>>>(out);
    {
        size_t tb = sizeof(g_cubtmp);
        cub::DeviceRadixSort::SortKeys(p_tmp, tb, (const u64*)p_k2, (u64*)p_k2o,
                                       2 * MCAND, 0, 48);
    }

    for (int l = 0; l < 5; l++) {
        dim3 g(hT[l], hT[l], 2);
        mask_kernel<<<g, 128>>>(l);
    }

    scan_kernel<<<2, 32>>>(out);
}